// round 10
// baseline (speedup 1.0000x reference)
#include <cuda_runtime.h>
#include <cstdint>

#define BB_  4
#define NN_  2048
#define CC_  512
#define HH_  8
#define HD_  64
// q pre-scale: (1/sqrt(64)) * log2(e)  -> scores arrive in log2 domain
#define QSCALE_ 0.18033688011112042f

// d_out layout: [ out (B*N*C) | k (B*H*N*hd) | v (B*H*N*hd) ]
#define KOFF_ (4u * 2048u * 512u)
#define VOFF_ (8u * 2048u * 512u)

// scratch
__device__ float g_q  [BB_ * HH_ * NN_ * HD_];   // pre-scaled q (log2 domain)
__device__ float g_ao [BB_ * NN_ * CC_];         // attention out [B,N,C]
__device__ float g_wt [1536 * 512];              // W_qkv^T  [N][K], tf32-rounded
__device__ float g_wtp[512 * 512];               // W_proj^T [N][K], tf32-rounded

// ===========================================================================
// m16n8k8 tf32 mma (base ISA, works on plain sm_103 target)
// ===========================================================================
__device__ __forceinline__ void mma_tf32(float (&d)[4], const uint32_t (&a)[4],
                                         const uint32_t (&b)[2]) {
    asm volatile(
        "mma.sync.aligned.m16n8k8.row.col.f32.tf32.tf32.f32 "
        "{%0,%1,%2,%3}, {%4,%5,%6,%7}, {%8,%9}, {%0,%1,%2,%3};"
        : "+f"(d[0]), "+f"(d[1]), "+f"(d[2]), "+f"(d[3])
        : "r"(a[0]), "r"(a[1]), "r"(a[2]), "r"(a[3]), "r"(b[0]), "r"(b[1]));
}

__device__ __forceinline__ uint32_t tf32_rna(float x) {
    uint32_t r;
    asm("cvt.rna.tf32.f32 %0, %1;" : "=r"(r) : "f"(x));
    return r;
}
__device__ __forceinline__ float rnaf(float x) {
    return __uint_as_float(tf32_rna(x));
}
__device__ __forceinline__ float4 rna4(float4 v) {
    v.x = rnaf(v.x); v.y = rnaf(v.y); v.z = rnaf(v.z); v.w = rnaf(v.w);
    return v;
}

// fast 2^t on fma/alu pipes only (no MUFU). t >= -100 clamped; |err| ~ 3e-6.
__device__ __forceinline__ float fexp2(float t) {
    t = fmaxf(t, -100.f);
    float z = t + 12582912.f;
    int   n = __float_as_int(z) - 0x4B400000;
    float f = t - (z - 12582912.f);
    float p =        1.3333558e-3f;
    p = fmaf(p, f, 9.6181291e-3f);
    p = fmaf(p, f, 5.5504109e-2f);
    p = fmaf(p, f, 2.4022651e-1f);
    p = fmaf(p, f, 6.9314718e-1f);
    p = fmaf(p, f, 1.0f);
    return __int_as_float(__float_as_int(p) + (n << 23));
}

// ===========================================================================
// W transpose + tf32 pre-round: src[R][C] -> dst[C][R] (dst in device code)
// which: 0 -> g_wt, 1 -> g_wtp
// ===========================================================================
__global__ void transpose_kernel(const float* __restrict__ src,
                                 int which, int R, int C)
{
    float* dst = which ? g_wtp : g_wt;
    __shared__ float tile[32][33];
    int bx = blockIdx.x * 32, by = blockIdx.y * 32;
#pragma unroll
    for (int i = 0; i < 32; i += 8)
        tile[threadIdx.y + i][threadIdx.x] =
            src[(size_t)(by + threadIdx.y + i) * C + bx + threadIdx.x];
    __syncthreads();
#pragma unroll
    for (int i = 0; i < 32; i += 8)
        dst[(size_t)(bx + threadIdx.y + i) * R + by + threadIdx.x] =
            rnaf(tile[threadIdx.x][threadIdx.y + i]);
}

// ===========================================================================
// tf32x2 mma GEMM mainloop (a_hi*b + a_lo*b; b pre-rounded in gmem).
// A split hi/lo ONCE at the SMEM store; fragment loops are pure LDS.
// C[128,128] = A[128,512] @ Bt[128,512]^T, both K-major ld=512.
// 256 threads = 8 warps (2m x 4n); warp tile 64m x 32n; acc[4][4][4].
// SMEM: sAhi/sAlo/sB, each [128][68]. 104448 B -> 2 CTAs/SM.
// ===========================================================================
#define GS_STR 68
#define G_SMEM_BYTES (3 * 128 * GS_STR * 4)    /* 104448 */

#define MMA_GEMM_BODY(APTR, BTPTR)                                              \
    extern __shared__ float gsm[];                                              \
    float* sAhi = gsm;                                                          \
    float* sAlo = gsm + 128 * GS_STR;                                           \
    float* sB   = gsm + 2 * 128 * GS_STR;                                       \
    const int t    = threadIdx.x;                                               \
    const int warp = t >> 5, lane = t & 31;                                     \
    const int wm   = warp >> 2, wn = warp & 3;                                  \
    const int lg   = lane >> 2, lq = lane & 3;                                  \
    const int row0 = blockIdx.y * 128, col0 = blockIdx.x * 128;                 \
    const float* Abase = (APTR) + (size_t)row0 * 512;                           \
    const float* Bbase = (BTPTR) + (size_t)col0 * 512;                          \
    float acc[4][4][4];                                                         \
    _Pragma("unroll") for (int i = 0; i < 4; i++)                               \
        _Pragma("unroll") for (int j = 0; j < 4; j++)                           \
            _Pragma("unroll") for (int c = 0; c < 4; c++) acc[i][j][c] = 0.f;   \
    for (int st = 0; st < 8; st++) {                                            \
        __syncthreads();                                                        \
        _Pragma("unroll 4")                                                     \
        for (int i = t; i < 2048; i += 256) {                                   \
            int j = i >> 4, d4 = (i & 15) * 4;                                  \
            float4 av = *reinterpret_cast<const float4*>(                       \
                Abase + (size_t)j * 512 + st * 64 + d4);                        \
            float4 bv = *reinterpret_cast<const float4*>(                       \
                Bbase + (size_t)j * 512 + st * 64 + d4);                        \
            float4 hi = rna4(av);                                               \
            float4 lo = make_float4(av.x - hi.x, av.y - hi.y,                   \
                                    av.z - hi.z, av.w - hi.w);                  \
            *reinterpret_cast<float4*>(&sAhi[j * GS_STR + d4]) = hi;            \
            *reinterpret_cast<float4*>(&sAlo[j * GS_STR + d4]) = lo;            \
            *reinterpret_cast<float4*>(&sB[j * GS_STR + d4]) = bv;              \
        }                                                                       \
        __syncthreads();                                                        \
        _Pragma("unroll")                                                       \
        for (int ks = 0; ks < 8; ks++) {                                        \
            const int k0 = ks * 8;                                              \
            uint32_t ahi[4][4], alo[4][4], bhi[4][2];                           \
            _Pragma("unroll")                                                   \
            for (int mf = 0; mf < 4; mf++) {                                    \
                int rA = wm * 64 + mf * 16 + lg;                                \
                ahi[mf][0] = __float_as_uint(sAhi[rA * GS_STR + k0 + lq]);      \
                ahi[mf][1] = __float_as_uint(sAhi[(rA + 8) * GS_STR + k0 + lq]);\
                ahi[mf][2] = __float_as_uint(sAhi[rA * GS_STR + k0 + lq + 4]);  \
                ahi[mf][3] = __float_as_uint(sAhi[(rA + 8) * GS_STR + k0 + lq + 4]); \
                alo[mf][0] = __float_as_uint(sAlo[rA * GS_STR + k0 + lq]);      \
                alo[mf][1] = __float_as_uint(sAlo[(rA + 8) * GS_STR + k0 + lq]);\
                alo[mf][2] = __float_as_uint(sAlo[rA * GS_STR + k0 + lq + 4]);  \
                alo[mf][3] = __float_as_uint(sAlo[(rA + 8) * GS_STR + k0 + lq + 4]); \
            }                                                                   \
            _Pragma("unroll")                                                   \
            for (int nf = 0; nf < 4; nf++) {                                    \
                int nb = wn * 32 + nf * 8 + lg;                                 \
                bhi[nf][0] = __float_as_uint(sB[nb * GS_STR + k0 + lq]);        \
                bhi[nf][1] = __float_as_uint(sB[nb * GS_STR + k0 + lq + 4]);    \
            }                                                                   \
            _Pragma("unroll")                                                   \
            for (int mf = 0; mf < 4; mf++)                                      \
                _Pragma("unroll")                                               \
                for (int nf = 0; nf < 4; nf++) {                                \
                    mma_tf32(acc[mf][nf], ahi[mf], bhi[nf]);                    \
                    mma_tf32(acc[mf][nf], alo[mf], bhi[nf]);                    \
                }                                                               \
        }                                                                       \
    }

// ---------------------------------------------------------------------------
// QKV GEMM (tf32x2 mma): q -> g_q (log2-scaled), k/v -> d_out [B,H,N,hd]
// ---------------------------------------------------------------------------
__global__ __launch_bounds__(256) void qkv_mma_kernel(
    const float* __restrict__ X, float* __restrict__ dout)
{
    MMA_GEMM_BODY(X, g_wt)

    const int s = col0 >> 9;                       // 0=q,1=k,2=v (block-uniform)
    const int h = ((col0 + wn * 32) >> 6) & 7;     // warp-uniform
#pragma unroll
    for (int mf = 0; mf < 4; mf++) {
        int m  = row0 + wm * 64 + mf * 16 + lg;
        int bb = m >> 11, n = m & 2047;
#pragma unroll
        for (int nf = 0; nf < 4; nf++) {
            int d = ((col0 + wn * 32 + nf * 8) & 63) + 2 * lq;
            size_t base0 = (((size_t)(bb * 8 + h)) * 2048 + n) * 64 + d;
            size_t base1 = base0 + 8 * 64;
            float2 v0 = make_float2(acc[mf][nf][0], acc[mf][nf][1]);
            float2 v1 = make_float2(acc[mf][nf][2], acc[mf][nf][3]);
            if (s == 0) {
                v0.x *= QSCALE_; v0.y *= QSCALE_;
                v1.x *= QSCALE_; v1.y *= QSCALE_;
                *reinterpret_cast<float2*>(&g_q[base0]) = v0;
                *reinterpret_cast<float2*>(&g_q[base1]) = v1;
            } else if (s == 1) {
                *reinterpret_cast<float2*>(dout + KOFF_ + base0) = v0;
                *reinterpret_cast<float2*>(dout + KOFF_ + base1) = v1;
            } else {
                *reinterpret_cast<float2*>(dout + VOFF_ + base0) = v0;
                *reinterpret_cast<float2*>(dout + VOFF_ + base1) = v1;
            }
        }
    }
}

// ---------------------------------------------------------------------------
// Proj GEMM (tf32x2 mma): g_ao @ W_proj + bias -> d_out[0..]
// ---------------------------------------------------------------------------
__global__ __launch_bounds__(256) void proj_mma_kernel(
    const float* __restrict__ bias, float* __restrict__ dout)
{
    MMA_GEMM_BODY(g_ao, g_wtp)

#pragma unroll
    for (int mf = 0; mf < 4; mf++) {
        int m = row0 + wm * 64 + mf * 16 + lg;
#pragma unroll
        for (int nf = 0; nf < 4; nf++) {
            int gcol = col0 + wn * 32 + nf * 8 + 2 * lq;
            float bx = bias[gcol], by = bias[gcol + 1];
            float* d0 = dout + (size_t)m * 512 + gcol;
            float* d1 = dout + (size_t)(m + 8) * 512 + gcol;
            *reinterpret_cast<float2*>(d0) =
                make_float2(acc[mf][nf][0] + bx, acc[mf][nf][1] + by);
            *reinterpret_cast<float2*>(d1) =
                make_float2(acc[mf][nf][2] + bx, acc[mf][nf][3] + by);
        }
    }
}

// ===========================================================================
// Flash attention: mma.sync tf32. QK^T = x2, PV = x1. All tf32 rounding
// hoisted to SMEM stores: Q split hi/lo once per block; K/V/P rounded once
// at store; fragment loops are pure LDS.
// SMEM: sQhi[64][68], sQlo[64][68], sK[128][68] (alias sP[64][132]),
//       sV[128][68], sRed[4][64] = 26368 floats = 105472 B, 2 CTAs/SM.
// ===========================================================================
#define SQ_STR 68
#define SK_STR 68
#define SV_STR 68
#define SP_STR 132
#define AT_FLOATS (2*64*SQ_STR + 8704 + 128*SV_STR + 4*64)
#define AT_BYTES  (AT_FLOATS * 4)

__global__ __launch_bounds__(256, 2) void attn_mma_kernel(const float* __restrict__ dkv)
{
    extern __shared__ float sm[];
    float* sQhi = sm;                        // [64][68]
    float* sQlo = sm + 64 * SQ_STR;          // [64][68]
    float* sK   = sm + 2 * 64 * SQ_STR;      // [128][68], aliased by sP[64][132]
    float* sP   = sK;
    float* sV   = sK + 8704;                 // [128][68]
    float* sRed = sV + 128 * SV_STR;         // [4][64]

    const int t    = threadIdx.x;
    const int warp = t >> 5, lane = t & 31;
    const int wm   = warp >> 2, wn = warp & 3;
    const int lg   = lane >> 2, lq = lane & 3;
    const int qt   = blockIdx.x, h = blockIdx.y, bb = blockIdx.z;

    const size_t bh = (size_t)(bb * 8 + h);
    const float* qb = g_q + (bh * 2048 + (size_t)qt * 64) * 64;
    const float* kb = dkv + KOFF_ + bh * 2048 * 64;
    const float* vb = dkv + VOFF_ + bh * 2048 * 64;

    // load Q tile [64][64], split hi/lo ONCE
#pragma unroll 4
    for (int i = t; i < 1024; i += 256) {
        int m = i >> 4, d4 = (i & 15) * 4;
        float4 v  = *reinterpret_cast<const float4*>(qb + m * 64 + d4);
        float4 hi = rna4(v);
        float4 lo = make_float4(v.x - hi.x, v.y - hi.y, v.z - hi.z, v.w - hi.w);
        *reinterpret_cast<float4*>(&sQhi[m * SQ_STR + d4]) = hi;
        *reinterpret_cast<float4*>(&sQlo[m * SQ_STR + d4]) = lo;
    }

    float o[2][2][4];
    float lsum[2][2];
#pragma unroll
    for (int mi = 0; mi < 2; mi++) {
        lsum[mi][0] = 0.f; lsum[mi][1] = 0.f;
#pragma unroll
        for (int nf = 0; nf < 2; nf++)
#pragma unroll
            for (int c = 0; c < 4; c++) o[mi][nf][c] = 0.f;
    }

    for (int j0 = 0; j0 < 2048; j0 += 128) {
        __syncthreads();
        // load K/V tiles, tf32-round at store
#pragma unroll 4
        for (int i = t; i < 2048; i += 256) {
            int j = i >> 4, d4 = (i & 15) * 4;
            float4 kv = *reinterpret_cast<const float4*>(kb + (size_t)(j0 + j) * 64 + d4);
            float4 vv = *reinterpret_cast<const float4*>(vb + (size_t)(j0 + j) * 64 + d4);
            *reinterpret_cast<float4*>(&sK[j * SK_STR + d4]) = rna4(kv);
            *reinterpret_cast<float4*>(&sV[j * SV_STR + d4]) = rna4(vv);
        }
        __syncthreads();

        float s[2][4][4];
#pragma unroll
        for (int mi = 0; mi < 2; mi++)
#pragma unroll
            for (int ni = 0; ni < 4; ni++)
#pragma unroll
                for (int c = 0; c < 4; c++) s[mi][ni][c] = 0.f;

#pragma unroll
        for (int ks = 0; ks < 8; ks++) {
            const int k0 = ks * 8;
            uint32_t ahi[2][4], alo[2][4], bhi[4][2];
#pragma unroll
            for (int mi = 0; mi < 2; mi++) {
                int rA = wm * 32 + mi * 16 + lg;
                ahi[mi][0] = __float_as_uint(sQhi[rA * SQ_STR + k0 + lq]);
                ahi[mi][1] = __float_as_uint(sQhi[(rA + 8) * SQ_STR + k0 + lq]);
                ahi[mi][2] = __float_as_uint(sQhi[rA * SQ_STR + k0 + lq + 4]);
                ahi[mi][3] = __float_as_uint(sQhi[(rA + 8) * SQ_STR + k0 + lq + 4]);
                alo[mi][0] = __float_as_uint(sQlo[rA * SQ_STR + k0 + lq]);
                alo[mi][1] = __float_as_uint(sQlo[(rA + 8) * SQ_STR + k0 + lq]);
                alo[mi][2] = __float_as_uint(sQlo[rA * SQ_STR + k0 + lq + 4]);
                alo[mi][3] = __float_as_uint(sQlo[(rA + 8) * SQ_STR + k0 + lq + 4]);
            }
#pragma unroll
            for (int ni = 0; ni < 4; ni++) {
                int nb = wn * 32 + ni * 8 + lg;
                bhi[ni][0] = __float_as_uint(sK[nb * SK_STR + k0 + lq]);
                bhi[ni][1] = __float_as_uint(sK[nb * SK_STR + k0 + lq + 4]);
            }
#pragma unroll
            for (int mi = 0; mi < 2; mi++)
#pragma unroll
                for (int ni = 0; ni < 4; ni++) {
                    mma_tf32(s[mi][ni], ahi[mi], bhi[ni]);
                    mma_tf32(s[mi][ni], alo[mi], bhi[ni]);
                }
        }
        __syncthreads();

        // P = 2^S, tf32-rounded at store; lsum accumulates the ROUNDED P
#pragma unroll
        for (int mi = 0; mi < 2; mi++) {
            int row = wm * 32 + mi * 16 + lg;
#pragma unroll
            for (int ni = 0; ni < 4; ni++) {
                float p0 = rnaf(fexp2(s[mi][ni][0]));
                float p1 = rnaf(fexp2(s[mi][ni][1]));
                float p2 = rnaf(fexp2(s[mi][ni][2]));
                float p3 = rnaf(fexp2(s[mi][ni][3]));
                lsum[mi][0] += p0 + p1;
                lsum[mi][1] += p2 + p3;
                int col = wn * 32 + ni * 8 + 2 * lq;
                *reinterpret_cast<float2*>(&sP[row * SP_STR + col]) = make_float2(p0, p1);
                *reinterpret_cast<float2*>(&sP[(row + 8) * SP_STR + col]) = make_float2(p2, p3);
            }
        }
        __syncthreads();

#pragma unroll
        for (int kk = 0; kk < 16; kk++) {
            const int k0 = kk * 8;
            uint32_t phi[2][4], bv[2][2];
#pragma unroll
            for (int mi = 0; mi < 2; mi++) {
                int rA = wm * 32 + mi * 16 + lg;
                phi[mi][0] = __float_as_uint(sP[rA * SP_STR + k0 + lq]);
                phi[mi][1] = __float_as_uint(sP[(rA + 8) * SP_STR + k0 + lq]);
                phi[mi][2] = __float_as_uint(sP[rA * SP_STR + k0 + lq + 4]);
                phi[mi][3] = __float_as_uint(sP[(rA + 8) * SP_STR + k0 + lq + 4]);
            }
#pragma unroll
            for (int nf = 0; nf < 2; nf++) {
                int nb = wn * 16 + nf * 8 + lg;
                bv[nf][0] = __float_as_uint(sV[(k0 + lq) * SV_STR + nb]);
                bv[nf][1] = __float_as_uint(sV[(k0 + lq + 4) * SV_STR + nb]);
            }
#pragma unroll
            for (int mi = 0; mi < 2; mi++)
#pragma unroll
                for (int nf = 0; nf < 2; nf++)
                    mma_tf32(o[mi][nf], phi[mi], bv[nf]);
        }
    }

#pragma unroll
    for (int mi = 0; mi < 2; mi++)
#pragma unroll
        for (int hf = 0; hf < 2; hf++) {
            float v = lsum[mi][hf];
            v += __shfl_xor_sync(0xffffffffu, v, 1);
            v += __shfl_xor_sync(0xffffffffu, v, 2);
            lsum[mi][hf] = v;
            if (lq == 0)
                sRed[wn * 64 + wm * 32 + mi * 16 + lg + 8 * hf] = v;
        }
    __syncthreads();

#pragma unroll
    for (int mi = 0; mi < 2; mi++) {
        int row = wm * 32 + mi * 16 + lg;
        float l0 = sRed[0 * 64 + row] + sRed[1 * 64 + row] +
                   sRed[2 * 64 + row] + sRed[3 * 64 + row];
        float l1 = sRed[0 * 64 + row + 8] + sRed[1 * 64 + row + 8] +
                   sRed[2 * 64 + row + 8] + sRed[3 * 64 + row + 8];
        float inv0 = __fdividef(1.f, l0);
        float inv1 = __fdividef(1.f, l1);
        int n0 = qt * 64 + row;
#pragma unroll
        for (int nf = 0; nf < 2; nf++) {
            int col = h * 64 + wn * 16 + nf * 8 + 2 * lq;
            float* d0 = g_ao + ((size_t)bb * 2048 + n0) * 512 + col;
            float* d1 = g_ao + ((size_t)bb * 2048 + n0 + 8) * 512 + col;
            *reinterpret_cast<float2*>(d0) =
                make_float2(o[mi][nf][0] * inv0, o[mi][nf][1] * inv0);
            *reinterpret_cast<float2*>(d1) =
                make_float2(o[mi][nf][2] * inv1, o[mi][nf][3] * inv1);
        }
    }
}

// ===========================================================================
extern "C" void kernel_launch(void* const* d_in, const int* in_sizes, int n_in,
                              void* d_out, int out_size)
{
    const float* x     = (const float*)d_in[0];
    const float* wqkv  = (const float*)d_in[1];
    const float* wproj = (const float*)d_in[2];
    const float* bproj = (const float*)d_in[3];
    float* out = (float*)d_out;

    cudaFuncSetAttribute(attn_mma_kernel,
                         cudaFuncAttributeMaxDynamicSharedMemorySize, AT_BYTES);
    cudaFuncSetAttribute(qkv_mma_kernel,
                         cudaFuncAttributeMaxDynamicSharedMemorySize, G_SMEM_BYTES);
    cudaFuncSetAttribute(proj_mma_kernel,
                         cudaFuncAttributeMaxDynamicSharedMemorySize, G_SMEM_BYTES);

    transpose_kernel<<<dim3(48, 16), dim3(32, 8)>>>(wqkv,  0, 512, 1536);
    transpose_kernel<<<dim3(16, 16), dim3(32, 8)>>>(wproj, 1, 512, 512);

    qkv_mma_kernel <<<dim3(12, 64), 256, G_SMEM_BYTES>>>(x, out);
    attn_mma_kernel<<<dim3(32, 8, 4), 256, AT_BYTES>>>(out);
    proj_mma_kernel<<<dim3(4, 64), 256, G_SMEM_BYTES>>>(bproj, out);
}

// round 11
// speedup vs baseline: 1.2318x; 1.2318x over previous
#include <cuda_runtime.h>
#include <cstdint>

#define BB_  4
#define NN_  2048
#define CC_  512
#define HH_  8
#define HD_  64
// q pre-scale: (1/sqrt(64)) * log2(e)  -> scores arrive in log2 domain
#define QSCALE_ 0.18033688011112042f

// d_out layout: [ out (B*N*C) | k (B*H*N*hd) | v (B*H*N*hd) ]
#define KOFF_ (4u * 2048u * 512u)
#define VOFF_ (8u * 2048u * 512u)

// scratch
__device__ float g_q  [BB_ * HH_ * NN_ * HD_];   // pre-scaled q (log2 domain)
__device__ float g_ao [BB_ * NN_ * CC_];         // attention out [B,N,C]
__device__ float g_wt [1536 * 512];              // W_qkv^T  [N][K], tf32-rounded
__device__ float g_wtp[512 * 512];               // W_proj^T [N][K], tf32-rounded

// ===========================================================================
// m16n8k8 tf32 mma (base ISA, works on plain sm_103 target)
// ===========================================================================
__device__ __forceinline__ void mma_tf32(float (&d)[4], const uint32_t (&a)[4],
                                         const uint32_t (&b)[2]) {
    asm volatile(
        "mma.sync.aligned.m16n8k8.row.col.f32.tf32.tf32.f32 "
        "{%0,%1,%2,%3}, {%4,%5,%6,%7}, {%8,%9}, {%0,%1,%2,%3};"
        : "+f"(d[0]), "+f"(d[1]), "+f"(d[2]), "+f"(d[3])
        : "r"(a[0]), "r"(a[1]), "r"(a[2]), "r"(a[3]), "r"(b[0]), "r"(b[1]));
}

__device__ __forceinline__ uint32_t tf32_rna(float x) {
    uint32_t r;
    asm("cvt.rna.tf32.f32 %0, %1;" : "=r"(r) : "f"(x));
    return r;
}
__device__ __forceinline__ float rnaf(float x) {
    return __uint_as_float(tf32_rna(x));
}
__device__ __forceinline__ float4 rna4(float4 v) {
    v.x = rnaf(v.x); v.y = rnaf(v.y); v.z = rnaf(v.z); v.w = rnaf(v.w);
    return v;
}

// fast 2^t on fma/alu pipes only (no MUFU). t >= -100 clamped; |err| ~ 3e-6.
__device__ __forceinline__ float fexp2(float t) {
    t = fmaxf(t, -100.f);
    float z = t + 12582912.f;
    int   n = __float_as_int(z) - 0x4B400000;
    float f = t - (z - 12582912.f);
    float p =        1.3333558e-3f;
    p = fmaf(p, f, 9.6181291e-3f);
    p = fmaf(p, f, 5.5504109e-2f);
    p = fmaf(p, f, 2.4022651e-1f);
    p = fmaf(p, f, 6.9314718e-1f);
    p = fmaf(p, f, 1.0f);
    return __int_as_float(__float_as_int(p) + (n << 23));
}

// ===========================================================================
// W transpose + tf32 pre-round: src[R][C] -> dst[C][R] (dst in device code)
// which: 0 -> g_wt, 1 -> g_wtp
// ===========================================================================
__global__ void transpose_kernel(const float* __restrict__ src,
                                 int which, int R, int C)
{
    float* dst = which ? g_wtp : g_wt;
    __shared__ float tile[32][33];
    int bx = blockIdx.x * 32, by = blockIdx.y * 32;
#pragma unroll
    for (int i = 0; i < 32; i += 8)
        tile[threadIdx.y + i][threadIdx.x] =
            src[(size_t)(by + threadIdx.y + i) * C + bx + threadIdx.x];
    __syncthreads();
#pragma unroll
    for (int i = 0; i < 32; i += 8)
        dst[(size_t)(bx + threadIdx.y + i) * R + by + threadIdx.x] =
            rnaf(tile[threadIdx.x][threadIdx.y + i]);
}

// ===========================================================================
// tf32x2 mma GEMM mainloop (R9 structure; B pre-rounded in gmem so no B cvt;
// A split hi/lo in registers at fragment read — no extra SMEM buffer).
// C[128,128] = A[128,512] @ Bt[128,512]^T, both K-major ld=512.
// 256 threads = 8 warps (2m x 4n); warp tile 64m x 32n; acc[4][4][4].
// ===========================================================================
#define GS_STR 68
#define G_SMEM_BYTES (2 * 128 * GS_STR * 4)    /* 69632 */

#define MMA_GEMM_BODY(APTR, BTPTR)                                              \
    extern __shared__ float gsm[];                                              \
    float* sA = gsm;                                                            \
    float* sB = gsm + 128 * GS_STR;                                             \
    const int t    = threadIdx.x;                                               \
    const int warp = t >> 5, lane = t & 31;                                     \
    const int wm   = warp >> 2, wn = warp & 3;                                  \
    const int lg   = lane >> 2, lq = lane & 3;                                  \
    const int row0 = blockIdx.y * 128, col0 = blockIdx.x * 128;                 \
    const float* Abase = (APTR) + (size_t)row0 * 512;                           \
    const float* Bbase = (BTPTR) + (size_t)col0 * 512;                          \
    float acc[4][4][4];                                                         \
    _Pragma("unroll") for (int i = 0; i < 4; i++)                               \
        _Pragma("unroll") for (int j = 0; j < 4; j++)                           \
            _Pragma("unroll") for (int c = 0; c < 4; c++) acc[i][j][c] = 0.f;   \
    for (int st = 0; st < 8; st++) {                                            \
        __syncthreads();                                                        \
        _Pragma("unroll 4")                                                     \
        for (int i = t; i < 2048; i += 256) {                                   \
            int j = i >> 4, d4 = (i & 15) * 4;                                  \
            float4 av = *reinterpret_cast<const float4*>(                       \
                Abase + (size_t)j * 512 + st * 64 + d4);                        \
            float4 bv = *reinterpret_cast<const float4*>(                       \
                Bbase + (size_t)j * 512 + st * 64 + d4);                        \
            *reinterpret_cast<float4*>(&sA[j * GS_STR + d4]) = av;              \
            *reinterpret_cast<float4*>(&sB[j * GS_STR + d4]) = bv;              \
        }                                                                       \
        __syncthreads();                                                        \
        _Pragma("unroll")                                                       \
        for (int ks = 0; ks < 8; ks++) {                                        \
            const int k0 = ks * 8;                                              \
            uint32_t ahi[4][4], alo[4][4], bhi[4][2];                           \
            _Pragma("unroll")                                                   \
            for (int mf = 0; mf < 4; mf++) {                                    \
                int rA = wm * 64 + mf * 16 + lg;                                \
                float f0 = sA[rA * GS_STR + k0 + lq];                           \
                float f1 = sA[(rA + 8) * GS_STR + k0 + lq];                     \
                float f2 = sA[rA * GS_STR + k0 + lq + 4];                       \
                float f3 = sA[(rA + 8) * GS_STR + k0 + lq + 4];                 \
                ahi[mf][0] = tf32_rna(f0);                                      \
                alo[mf][0] = __float_as_uint(f0 - __uint_as_float(ahi[mf][0])); \
                ahi[mf][1] = tf32_rna(f1);                                      \
                alo[mf][1] = __float_as_uint(f1 - __uint_as_float(ahi[mf][1])); \
                ahi[mf][2] = tf32_rna(f2);                                      \
                alo[mf][2] = __float_as_uint(f2 - __uint_as_float(ahi[mf][2])); \
                ahi[mf][3] = tf32_rna(f3);                                      \
                alo[mf][3] = __float_as_uint(f3 - __uint_as_float(ahi[mf][3])); \
            }                                                                   \
            _Pragma("unroll")                                                   \
            for (int nf = 0; nf < 4; nf++) {                                    \
                int nb = wn * 32 + nf * 8 + lg;                                 \
                bhi[nf][0] = __float_as_uint(sB[nb * GS_STR + k0 + lq]);        \
                bhi[nf][1] = __float_as_uint(sB[nb * GS_STR + k0 + lq + 4]);    \
            }                                                                   \
            _Pragma("unroll")                                                   \
            for (int mf = 0; mf < 4; mf++)                                      \
                _Pragma("unroll")                                               \
                for (int nf = 0; nf < 4; nf++) {                                \
                    mma_tf32(acc[mf][nf], ahi[mf], bhi[nf]);                    \
                    mma_tf32(acc[mf][nf], alo[mf], bhi[nf]);                    \
                }                                                               \
        }                                                                       \
    }

// ---------------------------------------------------------------------------
// QKV GEMM (tf32x2 mma): q -> g_q (log2-scaled), k/v -> d_out [B,H,N,hd]
// ---------------------------------------------------------------------------
__global__ __launch_bounds__(256) void qkv_mma_kernel(
    const float* __restrict__ X, float* __restrict__ dout)
{
    MMA_GEMM_BODY(X, g_wt)

    const int s = col0 >> 9;                       // 0=q,1=k,2=v (block-uniform)
    const int h = ((col0 + wn * 32) >> 6) & 7;     // warp-uniform
#pragma unroll
    for (int mf = 0; mf < 4; mf++) {
        int m  = row0 + wm * 64 + mf * 16 + lg;
        int bb = m >> 11, n = m & 2047;
#pragma unroll
        for (int nf = 0; nf < 4; nf++) {
            int d = ((col0 + wn * 32 + nf * 8) & 63) + 2 * lq;
            size_t base0 = (((size_t)(bb * 8 + h)) * 2048 + n) * 64 + d;
            size_t base1 = base0 + 8 * 64;
            float2 v0 = make_float2(acc[mf][nf][0], acc[mf][nf][1]);
            float2 v1 = make_float2(acc[mf][nf][2], acc[mf][nf][3]);
            if (s == 0) {
                v0.x *= QSCALE_; v0.y *= QSCALE_;
                v1.x *= QSCALE_; v1.y *= QSCALE_;
                *reinterpret_cast<float2*>(&g_q[base0]) = v0;
                *reinterpret_cast<float2*>(&g_q[base1]) = v1;
            } else if (s == 1) {
                *reinterpret_cast<float2*>(dout + KOFF_ + base0) = v0;
                *reinterpret_cast<float2*>(dout + KOFF_ + base1) = v1;
            } else {
                *reinterpret_cast<float2*>(dout + VOFF_ + base0) = v0;
                *reinterpret_cast<float2*>(dout + VOFF_ + base1) = v1;
            }
        }
    }
}

// ---------------------------------------------------------------------------
// Proj GEMM (tf32x2 mma): g_ao @ W_proj + bias -> d_out[0..]
// ---------------------------------------------------------------------------
__global__ __launch_bounds__(256) void proj_mma_kernel(
    const float* __restrict__ bias, float* __restrict__ dout)
{
    MMA_GEMM_BODY(g_ao, g_wtp)

#pragma unroll
    for (int mf = 0; mf < 4; mf++) {
        int m = row0 + wm * 64 + mf * 16 + lg;
#pragma unroll
        for (int nf = 0; nf < 4; nf++) {
            int gcol = col0 + wn * 32 + nf * 8 + 2 * lq;
            float bx = bias[gcol], by = bias[gcol + 1];
            float* d0 = dout + (size_t)m * 512 + gcol;
            float* d1 = dout + (size_t)(m + 8) * 512 + gcol;
            *reinterpret_cast<float2*>(d0) =
                make_float2(acc[mf][nf][0] + bx, acc[mf][nf][1] + by);
            *reinterpret_cast<float2*>(d1) =
                make_float2(acc[mf][nf][2] + bx, acc[mf][nf][3] + by);
        }
    }
}

// ===========================================================================
// Flash attention: mma.sync tf32. QK^T = x1 (rna Q * rna K),
// PV = x1 (rna P * rna V). All rounding at SMEM stores, zero extra LDS:
// sQ rounded once per block; K/V rounded at tile load; P rounded at store.
// SMEM identical footprint to verified R9: 90112 B, 2 CTAs/SM.
// ===========================================================================
#define SQ_STR 68
#define SK_STR 68
#define SV_STR 72
#define SP_STR 132
#define AT_FLOATS (64*SQ_STR + 8704 + 128*SV_STR + 4*64)
#define AT_BYTES  (AT_FLOATS * 4)

__global__ __launch_bounds__(256, 2) void attn_mma_kernel(const float* __restrict__ dkv)
{
    extern __shared__ float sm[];
    float* sQ   = sm;                       // [64][68], tf32-rounded
    float* sK   = sm + 64 * SQ_STR;         // [128][68], aliased by sP[64][132]
    float* sP   = sK;
    float* sV   = sK + 8704;                // [128][72]
    float* sRed = sV + 128 * SV_STR;        // [4][64]

    const int t    = threadIdx.x;
    const int warp = t >> 5, lane = t & 31;
    const int wm   = warp >> 2, wn = warp & 3;
    const int lg   = lane >> 2, lq = lane & 3;
    const int qt   = blockIdx.x, h = blockIdx.y, bb = blockIdx.z;

    const size_t bh = (size_t)(bb * 8 + h);
    const float* qb = g_q + (bh * 2048 + (size_t)qt * 64) * 64;
    const float* kb = dkv + KOFF_ + bh * 2048 * 64;
    const float* vb = dkv + VOFF_ + bh * 2048 * 64;

    // load Q tile [64][64], tf32-round once
#pragma unroll 4
    for (int i = t; i < 1024; i += 256) {
        int m = i >> 4, d4 = (i & 15) * 4;
        float4 v = *reinterpret_cast<const float4*>(qb + m * 64 + d4);
        *reinterpret_cast<float4*>(&sQ[m * SQ_STR + d4]) = rna4(v);
    }

    float o[2][2][4];
    float lsum[2][2];
#pragma unroll
    for (int mi = 0; mi < 2; mi++) {
        lsum[mi][0] = 0.f; lsum[mi][1] = 0.f;
#pragma unroll
        for (int nf = 0; nf < 2; nf++)
#pragma unroll
            for (int c = 0; c < 4; c++) o[mi][nf][c] = 0.f;
    }

    for (int j0 = 0; j0 < 2048; j0 += 128) {
        __syncthreads();
        // load K/V tiles, tf32-round at store
#pragma unroll 4
        for (int i = t; i < 2048; i += 256) {
            int j = i >> 4, d4 = (i & 15) * 4;
            float4 kv = *reinterpret_cast<const float4*>(kb + (size_t)(j0 + j) * 64 + d4);
            float4 vv = *reinterpret_cast<const float4*>(vb + (size_t)(j0 + j) * 64 + d4);
            *reinterpret_cast<float4*>(&sK[j * SK_STR + d4]) = rna4(kv);
            *reinterpret_cast<float4*>(&sV[j * SV_STR + d4]) = rna4(vv);
        }
        __syncthreads();

        float s[2][4][4];
#pragma unroll
        for (int mi = 0; mi < 2; mi++)
#pragma unroll
            for (int ni = 0; ni < 4; ni++)
#pragma unroll
                for (int c = 0; c < 4; c++) s[mi][ni][c] = 0.f;

#pragma unroll
        for (int ks = 0; ks < 8; ks++) {
            const int k0 = ks * 8;
            uint32_t a[2][4], b[4][2];
#pragma unroll
            for (int mi = 0; mi < 2; mi++) {
                int rA = wm * 32 + mi * 16 + lg;
                a[mi][0] = __float_as_uint(sQ[rA * SQ_STR + k0 + lq]);
                a[mi][1] = __float_as_uint(sQ[(rA + 8) * SQ_STR + k0 + lq]);
                a[mi][2] = __float_as_uint(sQ[rA * SQ_STR + k0 + lq + 4]);
                a[mi][3] = __float_as_uint(sQ[(rA + 8) * SQ_STR + k0 + lq + 4]);
            }
#pragma unroll
            for (int ni = 0; ni < 4; ni++) {
                int nb = wn * 32 + ni * 8 + lg;
                b[ni][0] = __float_as_uint(sK[nb * SK_STR + k0 + lq]);
                b[ni][1] = __float_as_uint(sK[nb * SK_STR + k0 + lq + 4]);
            }
#pragma unroll
            for (int mi = 0; mi < 2; mi++)
#pragma unroll
                for (int ni = 0; ni < 4; ni++)
                    mma_tf32(s[mi][ni], a[mi], b[ni]);
        }
        __syncthreads();

        // P = 2^S, tf32-rounded at store; lsum accumulates the ROUNDED P
#pragma unroll
        for (int mi = 0; mi < 2; mi++) {
            int row = wm * 32 + mi * 16 + lg;
#pragma unroll
            for (int ni = 0; ni < 4; ni++) {
                float p0 = rnaf(fexp2(s[mi][ni][0]));
                float p1 = rnaf(fexp2(s[mi][ni][1]));
                float p2 = rnaf(fexp2(s[mi][ni][2]));
                float p3 = rnaf(fexp2(s[mi][ni][3]));
                lsum[mi][0] += p0 + p1;
                lsum[mi][1] += p2 + p3;
                int col = wn * 32 + ni * 8 + 2 * lq;
                *reinterpret_cast<float2*>(&sP[row * SP_STR + col]) = make_float2(p0, p1);
                *reinterpret_cast<float2*>(&sP[(row + 8) * SP_STR + col]) = make_float2(p2, p3);
            }
        }
        __syncthreads();

#pragma unroll
        for (int kk = 0; kk < 16; kk++) {
            const int k0 = kk * 8;
            uint32_t phi[2][4], bv[2][2];
#pragma unroll
            for (int mi = 0; mi < 2; mi++) {
                int rA = wm * 32 + mi * 16 + lg;
                phi[mi][0] = __float_as_uint(sP[rA * SP_STR + k0 + lq]);
                phi[mi][1] = __float_as_uint(sP[(rA + 8) * SP_STR + k0 + lq]);
                phi[mi][2] = __float_as_uint(sP[rA * SP_STR + k0 + lq + 4]);
                phi[mi][3] = __float_as_uint(sP[(rA + 8) * SP_STR + k0 + lq + 4]);
            }
#pragma unroll
            for (int nf = 0; nf < 2; nf++) {
                int nb = wn * 16 + nf * 8 + lg;
                bv[nf][0] = __float_as_uint(sV[(k0 + lq) * SV_STR + nb]);
                bv[nf][1] = __float_as_uint(sV[(k0 + lq + 4) * SV_STR + nb]);
            }
#pragma unroll
            for (int mi = 0; mi < 2; mi++)
#pragma unroll
                for (int nf = 0; nf < 2; nf++)
                    mma_tf32(o[mi][nf], phi[mi], bv[nf]);
        }
    }

#pragma unroll
    for (int mi = 0; mi < 2; mi++)
#pragma unroll
        for (int hf = 0; hf < 2; hf++) {
            float v = lsum[mi][hf];
            v += __shfl_xor_sync(0xffffffffu, v, 1);
            v += __shfl_xor_sync(0xffffffffu, v, 2);
            lsum[mi][hf] = v;
            if (lq == 0)
                sRed[wn * 64 + wm * 32 + mi * 16 + lg + 8 * hf] = v;
        }
    __syncthreads();

#pragma unroll
    for (int mi = 0; mi < 2; mi++) {
        int row = wm * 32 + mi * 16 + lg;
        float l0 = sRed[0 * 64 + row] + sRed[1 * 64 + row] +
                   sRed[2 * 64 + row] + sRed[3 * 64 + row];
        float l1 = sRed[0 * 64 + row + 8] + sRed[1 * 64 + row + 8] +
                   sRed[2 * 64 + row + 8] + sRed[3 * 64 + row + 8];
        float inv0 = __fdividef(1.f, l0);
        float inv1 = __fdividef(1.f, l1);
        int n0 = qt * 64 + row;
#pragma unroll
        for (int nf = 0; nf < 2; nf++) {
            int col = h * 64 + wn * 16 + nf * 8 + 2 * lq;
            float* d0 = g_ao + ((size_t)bb * 2048 + n0) * 512 + col;
            float* d1 = g_ao + ((size_t)bb * 2048 + n0 + 8) * 512 + col;
            *reinterpret_cast<float2*>(d0) =
                make_float2(o[mi][nf][0] * inv0, o[mi][nf][1] * inv0);
            *reinterpret_cast<float2*>(d1) =
                make_float2(o[mi][nf][2] * inv1, o[mi][nf][3] * inv1);
        }
    }
}

// ===========================================================================
extern "C" void kernel_launch(void* const* d_in, const int* in_sizes, int n_in,
                              void* d_out, int out_size)
{
    const float* x     = (const float*)d_in[0];
    const float* wqkv  = (const float*)d_in[1];
    const float* wproj = (const float*)d_in[2];
    const float* bproj = (const float*)d_in[3];
    float* out = (float*)d_out;

    cudaFuncSetAttribute(attn_mma_kernel,
                         cudaFuncAttributeMaxDynamicSharedMemorySize, AT_BYTES);
    cudaFuncSetAttribute(qkv_mma_kernel,
                         cudaFuncAttributeMaxDynamicSharedMemorySize, G_SMEM_BYTES);
    cudaFuncSetAttribute(proj_mma_kernel,
                         cudaFuncAttributeMaxDynamicSharedMemorySize, G_SMEM_BYTES);

    transpose_kernel<<<dim3(48, 16), dim3(32, 8)>>>(wqkv,  0, 512, 1536);
    transpose_kernel<<<dim3(16, 16), dim3(32, 8)>>>(wproj, 1, 512, 512);

    qkv_mma_kernel <<<dim3(12, 64), 256, G_SMEM_BYTES>>>(x, out);
    attn_mma_kernel<<<dim3(32, 8, 4), 256, AT_BYTES>>>(out);
    proj_mma_kernel<<<dim3(4, 64), 256, G_SMEM_BYTES>>>(bproj, out);
}